// round 14
// baseline (speedup 1.0000x reference)
#include <cuda_runtime.h>
#include <math.h>

// Shapes are fixed by the dataset: B=8, H=8, T=4096, D=64, chunk=64.
#define BH_   64
#define NT_   64
#define BT_   64
#define DK_   64
#define DV_   64
#define T_    4096
#define VSPLIT 2
#define VW    (DV_/VSPLIT)           // 32
#define LOG2E_F 1.4426950408889634f
#define SCALE_F 0.125f               // 64^-0.5

// -------- scratch (static device globals; no runtime allocation) --------
__device__ float g_C[(size_t)BH_ * NT_ * DK_ * DV_];   // 64 MB: chunk-entry C states
__device__ float g_n[BH_ * NT_ * DK_];                 // chunk-entry n states
__device__ float g_m[BH_ * NT_];                       // chunk-entry m states
__device__ float g_b[BH_ * NT_ * BT_];                 // per-chunk cumsum(vecF)

// =======================================================================
// Pass 1: per-sequence scan over chunks. Computes carries (C, n, m),
// writes the ENTRY state of each chunk to global scratch.
// grid: (BH_, VSPLIT), block: 256. Each block owns C[:, vh*32 : vh*32+32]
// in registers (8 floats / thread) for the whole sequence.
// =======================================================================
__global__ void __launch_bounds__(256) mlstm_pass1(
    const float* __restrict__ k, const float* __restrict__ v,
    const float* __restrict__ iv, const float* __restrict__ fv)
{
    const int seq = blockIdx.x;
    const int vh  = blockIdx.y;
    const int tid = threadIdx.x;
    const int kk  = tid & 63;        // K-row of C this thread owns
    const int jg  = tid >> 6;        // 0..3 -> 8 V-cols each

    __shared__ float  ks_s[BT_ * DK_];
    __shared__ float4 vs4[BT_ * (VW / 4)];
    __shared__ float  vf_s[BT_], vi_s[BT_], b_s[BT_], g_s[BT_], ef_s[BT_];
    __shared__ float  n_s[DK_];
    __shared__ float  sc_s[2];

    float Creg[8];
#pragma unroll
    for (int u = 0; u < 8; u++) Creg[u] = 0.f;
    if (tid < DK_) n_s[tid] = 0.f;
    float m_run = 0.f;

    const size_t seqT = (size_t)seq * T_;

    for (int t = 0; t < NT_; t++) {
        const size_t base = seqT + (size_t)t * BT_;

        // per-element gates (log-sigmoid in log2 domain)
        if (tid < BT_) {
            float x = fv[base + tid];
            vf_s[tid] = LOG2E_F * (fminf(x, 0.f) - log1pf(expf(-fabsf(x))));
            vi_s[tid] = LOG2E_F * iv[base + tid];
        }
        // load k tile (64x64) and v half-tile (64xVW)
        for (int idx = tid; idx < BT_ * (DK_ / 4); idx += 256) {
            int r = idx >> 4, cq = (idx & 15) * 4;
            *(float4*)&ks_s[r * DK_ + cq] =
                *(const float4*)&k[(base + r) * DK_ + cq];
        }
        for (int idx = tid; idx < BT_ * (VW / 4); idx += 256) {
            int r = idx >> 3, jq = idx & 7;
            vs4[idx] = *(const float4*)&v[(base + r) * DV_ + vh * VW + jq * 4];
        }
        __syncthreads();

        // b = inclusive cumsum(vecF) (sequential order == jnp.cumsum semantics)
        if (tid < BT_) {
            float s = 0.f;
            for (int c = 0; c <= tid; c++) s += vf_s[c];
            b_s[tid] = s;
            if (vh == 0) g_b[(seq * NT_ + t) * BT_ + tid] = s;
        }
        __syncthreads();
        const float f_last = b_s[BT_ - 1];
        if (tid < BT_) g_s[tid] = vi_s[tid] + f_last - b_s[tid];
        __syncthreads();
        if (tid == 0) {
            float gm = -INFINITY;
            for (int c = 0; c < BT_; c++) gm = fmaxf(gm, g_s[c]);
            float m_next = fmaxf(f_last + m_run, gm);
            sc_s[0] = m_next;
            sc_s[1] = exp2f(f_last + m_run - m_next);
            if (vh == 0) g_m[seq * NT_ + t] = m_run;   // entry state
        }

        // snapshot entry C / n states (before update)
        {
            float* dst = &g_C[(((size_t)seq * NT_ + t) * DK_ + kk) * DV_
                              + vh * VW + jg * 8];
            *(float4*)dst       = make_float4(Creg[0], Creg[1], Creg[2], Creg[3]);
            *(float4*)(dst + 4) = make_float4(Creg[4], Creg[5], Creg[6], Creg[7]);
        }
        if (vh == 0 && tid < DK_) g_n[(seq * NT_ + t) * DK_ + tid] = n_s[tid];
        __syncthreads();

        const float m_next = sc_s[0], dec = sc_s[1];
        if (tid < BT_) ef_s[tid] = exp2f(g_s[tid] - m_next);
        __syncthreads();

        // C <- C*dec + (k*ef)^T @ v ;  n <- n*dec + colsum(k*ef)
        float acc[8];
#pragma unroll
        for (int u = 0; u < 8; u++) acc[u] = 0.f;
#pragma unroll 4
        for (int c = 0; c < BT_; c++) {
            float kv  = ks_s[c * DK_ + kk] * ef_s[c];
            float4 va = vs4[c * (VW / 4) + jg * 2];
            float4 vb = vs4[c * (VW / 4) + jg * 2 + 1];
            acc[0] += kv * va.x; acc[1] += kv * va.y;
            acc[2] += kv * va.z; acc[3] += kv * va.w;
            acc[4] += kv * vb.x; acc[5] += kv * vb.y;
            acc[6] += kv * vb.z; acc[7] += kv * vb.w;
        }
#pragma unroll
        for (int u = 0; u < 8; u++) Creg[u] = Creg[u] * dec + acc[u];

        if (vh == 0 && tid < DK_) {
            float na = 0.f;
            for (int c = 0; c < BT_; c++) na += ks_s[c * DK_ + tid] * ef_s[c];
            n_s[tid] = n_s[tid] * dec + na;
        }
        m_run = m_next;
        __syncthreads();
    }
}

// =======================================================================
// Pass 2: fully parallel per (seq, chunk). h = (qf*(q@C) + S@v) / denom.
// grid: (NT_, BH_), block: 256, dynamic smem ~83 KB.
// =======================================================================
#define P2_PAD 65
#define SMEM2_FLOATS (5 * BT_ * P2_PAD + 6 * BT_ + 4)
#define SMEM2_BYTES  (SMEM2_FLOATS * 4)

__global__ void __launch_bounds__(256) mlstm_pass2(
    const float* __restrict__ q, const float* __restrict__ k,
    const float* __restrict__ v, const float* __restrict__ iv,
    float* __restrict__ out)
{
    extern __shared__ float sm[];
    float* q_s   = sm;
    float* k_s   = q_s + BT_ * P2_PAD;
    float* v_s   = k_s + BT_ * P2_PAD;
    float* C_s   = v_s + BT_ * P2_PAD;
    float* S_s   = C_s + DK_ * P2_PAD;
    float* n_s   = S_s + BT_ * P2_PAD;   // 64
    float* b_s   = n_s + DK_;            // 64
    float* vi_s  = b_s + BT_;            // 64
    float* mt_s  = vi_s + BT_;           // 64
    float* qf_s  = mt_s + BT_;           // 64
    float* rden_s = qf_s + BT_;          // 64
    float* msc   = rden_s + BT_;         // 1

    const int t   = blockIdx.x;
    const int seq = blockIdx.y;
    const int tid = threadIdx.x;
    const size_t base = (size_t)seq * T_ + (size_t)t * BT_;
    const size_t stbase = ((size_t)seq * NT_ + t);

    // ---- loads: q,k,v tiles + entry-state C ----
    for (int idx = tid; idx < BT_ * 16; idx += 256) {
        int r = idx >> 4, cq = (idx & 15) * 4;
        float4 dq = *(const float4*)&q[(base + r) * DK_ + cq];
        float4 dk = *(const float4*)&k[(base + r) * DK_ + cq];
        float4 dv = *(const float4*)&v[(base + r) * DV_ + cq];
        float4 dc = *(const float4*)&g_C[(stbase * DK_ + r) * DV_ + cq];
        float* p;
        p = &q_s[r * P2_PAD + cq]; p[0]=dq.x; p[1]=dq.y; p[2]=dq.z; p[3]=dq.w;
        p = &k_s[r * P2_PAD + cq]; p[0]=dk.x; p[1]=dk.y; p[2]=dk.z; p[3]=dk.w;
        p = &v_s[r * P2_PAD + cq]; p[0]=dv.x; p[1]=dv.y; p[2]=dv.z; p[3]=dv.w;
        p = &C_s[r * P2_PAD + cq]; p[0]=dc.x; p[1]=dc.y; p[2]=dc.z; p[3]=dc.w;
    }
    if (tid < DK_) n_s[tid] = g_n[stbase * DK_ + tid];
    if (tid < BT_) {
        b_s[tid]  = g_b[stbase * BT_ + tid];
        vi_s[tid] = LOG2E_F * iv[base + tid];
    }
    if (tid == 0) msc[0] = g_m[stbase];
    __syncthreads();

    const float m_prev = msc[0];
    // m_total[r] = b[r] + max(m_prev, max_{c<=r}(vi[c]-b[c]))
    if (tid < BT_) {
        float am = -INFINITY;
        for (int c = 0; c <= tid; c++) am = fmaxf(am, vi_s[c] - b_s[c]);
        float mt = b_s[tid] + fmaxf(m_prev, am);
        mt_s[tid] = mt;
        qf_s[tid] = SCALE_F * exp2f(b_s[tid] + m_prev - mt);
    }
    __syncthreads();

    const int tc = tid & 15, tr = tid >> 4;
    const int r0 = tr * 4, c0 = tc * 4;

    // ---- S = (q@k^T) * scale * exp2(D - m_total), masked lower-tri ----
    {
        float dot[4][4];
#pragma unroll
        for (int u = 0; u < 4; u++)
#pragma unroll
            for (int w = 0; w < 4; w++) dot[u][w] = 0.f;
#pragma unroll 8
        for (int kkk = 0; kkk < DK_; kkk++) {
            float a[4], bb[4];
#pragma unroll
            for (int u = 0; u < 4; u++) a[u]  = q_s[(r0 + u) * P2_PAD + kkk];
#pragma unroll
            for (int w = 0; w < 4; w++) bb[w] = k_s[(c0 + w) * P2_PAD + kkk];
#pragma unroll
            for (int u = 0; u < 4; u++)
#pragma unroll
                for (int w = 0; w < 4; w++) dot[u][w] += a[u] * bb[w];
        }
#pragma unroll
        for (int u = 0; u < 4; u++) {
            int r = r0 + u;
#pragma unroll
            for (int w = 0; w < 4; w++) {
                int c = c0 + w;
                float sv = 0.f;
                if (c <= r)
                    sv = dot[u][w] * SCALE_F *
                         exp2f(vi_s[c] - b_s[c] + b_s[r] - mt_s[r]);
                S_s[r * P2_PAD + c] = sv;
            }
        }
    }
    __syncthreads();

    // ---- row sums + denominator ----
    if (tid < BT_) {
        int r = tid;
        float rs = 0.f;
        for (int c = 0; c < BT_; c++) rs += S_s[r * P2_PAD + c];
        float qn = 0.f;
        for (int kkk = 0; kkk < DK_; kkk++) qn += q_s[r * P2_PAD + kkk] * n_s[kkk];
        float dn = fmaxf(fabsf(qf_s[r] * qn + rs), exp2f(-mt_s[r]));
        rden_s[r] = 1.f / dn;
    }
    __syncthreads();

    // ---- h = (qf*(q@C) + S@v) * rden ----
    float acc1[4][4], acc2[4][4];
#pragma unroll
    for (int u = 0; u < 4; u++)
#pragma unroll
        for (int w = 0; w < 4; w++) { acc1[u][w] = 0.f; acc2[u][w] = 0.f; }

    const int j0 = tc * 4;
#pragma unroll 8
    for (int kkk = 0; kkk < DK_; kkk++) {
        float a[4], bb[4];
#pragma unroll
        for (int u = 0; u < 4; u++) a[u]  = q_s[(r0 + u) * P2_PAD + kkk];
#pragma unroll
        for (int w = 0; w < 4; w++) bb[w] = C_s[kkk * P2_PAD + j0 + w];
#pragma unroll
        for (int u = 0; u < 4; u++)
#pragma unroll
            for (int w = 0; w < 4; w++) acc1[u][w] += a[u] * bb[w];
    }
#pragma unroll 8
    for (int c = 0; c < BT_; c++) {
        float a[4], bb[4];
#pragma unroll
        for (int u = 0; u < 4; u++) a[u]  = S_s[(r0 + u) * P2_PAD + c];
#pragma unroll
        for (int w = 0; w < 4; w++) bb[w] = v_s[c * P2_PAD + j0 + w];
#pragma unroll
        for (int u = 0; u < 4; u++)
#pragma unroll
            for (int w = 0; w < 4; w++) acc2[u][w] += a[u] * bb[w];
    }

#pragma unroll
    for (int u = 0; u < 4; u++) {
        int r = r0 + u;
        float qf = qf_s[r], rd = rden_s[r];
        float4 o;
        o.x = (qf * acc1[u][0] + acc2[u][0]) * rd;
        o.y = (qf * acc1[u][1] + acc2[u][1]) * rd;
        o.z = (qf * acc1[u][2] + acc2[u][2]) * rd;
        o.w = (qf * acc1[u][3] + acc2[u][3]) * rd;
        *(float4*)&out[(base + r) * DV_ + j0] = o;
    }
}

// =======================================================================
extern "C" void kernel_launch(void* const* d_in, const int* in_sizes, int n_in,
                              void* d_out, int out_size)
{
    const float* q  = (const float*)d_in[0];
    const float* k  = (const float*)d_in[1];
    const float* v  = (const float*)d_in[2];
    const float* iv = (const float*)d_in[3];
    const float* fv = (const float*)d_in[4];
    float* out = (float*)d_out;

    cudaFuncSetAttribute(mlstm_pass2,
                         cudaFuncAttributeMaxDynamicSharedMemorySize,
                         SMEM2_BYTES);

    mlstm_pass1<<<dim3(BH_, VSPLIT), 256>>>(k, v, iv, fv);
    mlstm_pass2<<<dim3(NT_, BH_), 256, SMEM2_BYTES>>>(q, k, v, iv, out);
}

// round 15
// speedup vs baseline: 1.0032x; 1.0032x over previous
#include <cuda_runtime.h>
#include <math.h>

// Shapes are fixed by the dataset: B=8, H=8, T=4096, D=64, chunk=64.
#define BH_   64
#define NT_   64
#define BT_   64
#define DK_   64
#define DV_   64
#define T_    4096
#define VSPLIT 2
#define VW    (DV_/VSPLIT)           // 32
#define LOG2E_F 1.4426950408889634f
#define SCALE_F 0.125f               // 64^-0.5

// -------- scratch (static device globals; no runtime allocation) --------
__device__ float g_C[(size_t)BH_ * NT_ * DK_ * DV_];   // 64 MB: chunk-entry C states
__device__ float g_n[BH_ * NT_ * DK_];                 // chunk-entry n states
__device__ float g_m[BH_ * NT_];                       // chunk-entry m states
__device__ float g_b[BH_ * NT_ * BT_];                 // per-chunk cumsum(vecF)

// =======================================================================
// Pass 1: per-sequence scan over chunks. Computes carries (C, n, m),
// writes the ENTRY state of each chunk to global scratch.
// grid: (BH_, VSPLIT), block: 256. Each block owns C[:, vh*32 : vh*32+32]
// in registers (8 floats / thread) for the whole sequence.
// =======================================================================
__global__ void __launch_bounds__(256) mlstm_pass1(
    const float* __restrict__ k, const float* __restrict__ v,
    const float* __restrict__ iv, const float* __restrict__ fv)
{
    const int seq = blockIdx.x;
    const int vh  = blockIdx.y;
    const int tid = threadIdx.x;
    const int kk  = tid & 63;        // K-row of C this thread owns
    const int jg  = tid >> 6;        // 0..3 -> 8 V-cols each

    __shared__ float  ks_s[BT_ * DK_];
    __shared__ float4 vs4[BT_ * (VW / 4)];
    __shared__ float  vf_s[BT_], vi_s[BT_], b_s[BT_], g_s[BT_], ef_s[BT_];
    __shared__ float  n_s[DK_];
    __shared__ float  sc_s[2];

    float Creg[8];
#pragma unroll
    for (int u = 0; u < 8; u++) Creg[u] = 0.f;
    if (tid < DK_) n_s[tid] = 0.f;
    float m_run = 0.f;

    const size_t seqT = (size_t)seq * T_;

    for (int t = 0; t < NT_; t++) {
        const size_t base = seqT + (size_t)t * BT_;

        // per-element gates (log-sigmoid in log2 domain)
        if (tid < BT_) {
            float x = fv[base + tid];
            vf_s[tid] = LOG2E_F * (fminf(x, 0.f) - log1pf(expf(-fabsf(x))));
            vi_s[tid] = LOG2E_F * iv[base + tid];
        }
        // load k tile (64x64) and v half-tile (64xVW)
        for (int idx = tid; idx < BT_ * (DK_ / 4); idx += 256) {
            int r = idx >> 4, cq = (idx & 15) * 4;
            *(float4*)&ks_s[r * DK_ + cq] =
                *(const float4*)&k[(base + r) * DK_ + cq];
        }
        for (int idx = tid; idx < BT_ * (VW / 4); idx += 256) {
            int r = idx >> 3, jq = idx & 7;
            vs4[idx] = *(const float4*)&v[(base + r) * DV_ + vh * VW + jq * 4];
        }
        __syncthreads();

        // b = inclusive cumsum(vecF) (sequential order == jnp.cumsum semantics)
        if (tid < BT_) {
            float s = 0.f;
            for (int c = 0; c <= tid; c++) s += vf_s[c];
            b_s[tid] = s;
            if (vh == 0) g_b[(seq * NT_ + t) * BT_ + tid] = s;
        }
        __syncthreads();
        const float f_last = b_s[BT_ - 1];
        if (tid < BT_) g_s[tid] = vi_s[tid] + f_last - b_s[tid];
        __syncthreads();
        if (tid == 0) {
            float gm = -INFINITY;
            for (int c = 0; c < BT_; c++) gm = fmaxf(gm, g_s[c]);
            float m_next = fmaxf(f_last + m_run, gm);
            sc_s[0] = m_next;
            sc_s[1] = exp2f(f_last + m_run - m_next);
            if (vh == 0) g_m[seq * NT_ + t] = m_run;   // entry state
        }

        // snapshot entry C / n states (before update)
        {
            float* dst = &g_C[(((size_t)seq * NT_ + t) * DK_ + kk) * DV_
                              + vh * VW + jg * 8];
            *(float4*)dst       = make_float4(Creg[0], Creg[1], Creg[2], Creg[3]);
            *(float4*)(dst + 4) = make_float4(Creg[4], Creg[5], Creg[6], Creg[7]);
        }
        if (vh == 0 && tid < DK_) g_n[(seq * NT_ + t) * DK_ + tid] = n_s[tid];
        __syncthreads();

        const float m_next = sc_s[0], dec = sc_s[1];
        if (tid < BT_) ef_s[tid] = exp2f(g_s[tid] - m_next);
        __syncthreads();

        // C <- C*dec + (k*ef)^T @ v ;  n <- n*dec + colsum(k*ef)
        float acc[8];
#pragma unroll
        for (int u = 0; u < 8; u++) acc[u] = 0.f;
#pragma unroll 4
        for (int c = 0; c < BT_; c++) {
            float kv  = ks_s[c * DK_ + kk] * ef_s[c];
            float4 va = vs4[c * (VW / 4) + jg * 2];
            float4 vb = vs4[c * (VW / 4) + jg * 2 + 1];
            acc[0] += kv * va.x; acc[1] += kv * va.y;
            acc[2] += kv * va.z; acc[3] += kv * va.w;
            acc[4] += kv * vb.x; acc[5] += kv * vb.y;
            acc[6] += kv * vb.z; acc[7] += kv * vb.w;
        }
#pragma unroll
        for (int u = 0; u < 8; u++) Creg[u] = Creg[u] * dec + acc[u];

        if (vh == 0 && tid < DK_) {
            float na = 0.f;
            for (int c = 0; c < BT_; c++) na += ks_s[c * DK_ + tid] * ef_s[c];
            n_s[tid] = n_s[tid] * dec + na;
        }
        m_run = m_next;
        __syncthreads();
    }
}

// =======================================================================
// Pass 2: fully parallel per (seq, chunk). h = (qf*(q@C) + S@v) / denom.
// grid: (NT_, BH_), block: 256, dynamic smem ~83 KB.
// =======================================================================
#define P2_PAD 65
#define SMEM2_FLOATS (5 * BT_ * P2_PAD + 6 * BT_ + 4)
#define SMEM2_BYTES  (SMEM2_FLOATS * 4)

__global__ void __launch_bounds__(256) mlstm_pass2(
    const float* __restrict__ q, const float* __restrict__ k,
    const float* __restrict__ v, const float* __restrict__ iv,
    float* __restrict__ out)
{
    extern __shared__ float sm[];
    float* q_s   = sm;
    float* k_s   = q_s + BT_ * P2_PAD;
    float* v_s   = k_s + BT_ * P2_PAD;
    float* C_s   = v_s + BT_ * P2_PAD;
    float* S_s   = C_s + DK_ * P2_PAD;
    float* n_s   = S_s + BT_ * P2_PAD;   // 64
    float* b_s   = n_s + DK_;            // 64
    float* vi_s  = b_s + BT_;            // 64
    float* mt_s  = vi_s + BT_;           // 64
    float* qf_s  = mt_s + BT_;           // 64
    float* rden_s = qf_s + BT_;          // 64
    float* msc   = rden_s + BT_;         // 1

    const int t   = blockIdx.x;
    const int seq = blockIdx.y;
    const int tid = threadIdx.x;
    const size_t base = (size_t)seq * T_ + (size_t)t * BT_;
    const size_t stbase = ((size_t)seq * NT_ + t);

    // ---- loads: q,k,v tiles + entry-state C ----
    for (int idx = tid; idx < BT_ * 16; idx += 256) {
        int r = idx >> 4, cq = (idx & 15) * 4;
        float4 dq = *(const float4*)&q[(base + r) * DK_ + cq];
        float4 dk = *(const float4*)&k[(base + r) * DK_ + cq];
        float4 dv = *(const float4*)&v[(base + r) * DV_ + cq];
        float4 dc = *(const float4*)&g_C[(stbase * DK_ + r) * DV_ + cq];
        float* p;
        p = &q_s[r * P2_PAD + cq]; p[0]=dq.x; p[1]=dq.y; p[2]=dq.z; p[3]=dq.w;
        p = &k_s[r * P2_PAD + cq]; p[0]=dk.x; p[1]=dk.y; p[2]=dk.z; p[3]=dk.w;
        p = &v_s[r * P2_PAD + cq]; p[0]=dv.x; p[1]=dv.y; p[2]=dv.z; p[3]=dv.w;
        p = &C_s[r * P2_PAD + cq]; p[0]=dc.x; p[1]=dc.y; p[2]=dc.z; p[3]=dc.w;
    }
    if (tid < DK_) n_s[tid] = g_n[stbase * DK_ + tid];
    if (tid < BT_) {
        b_s[tid]  = g_b[stbase * BT_ + tid];
        vi_s[tid] = LOG2E_F * iv[base + tid];
    }
    if (tid == 0) msc[0] = g_m[stbase];
    __syncthreads();

    const float m_prev = msc[0];
    // m_total[r] = b[r] + max(m_prev, max_{c<=r}(vi[c]-b[c]))
    if (tid < BT_) {
        float am = -INFINITY;
        for (int c = 0; c <= tid; c++) am = fmaxf(am, vi_s[c] - b_s[c]);
        float mt = b_s[tid] + fmaxf(m_prev, am);
        mt_s[tid] = mt;
        qf_s[tid] = SCALE_F * exp2f(b_s[tid] + m_prev - mt);
    }
    __syncthreads();

    const int tc = tid & 15, tr = tid >> 4;
    const int r0 = tr * 4, c0 = tc * 4;

    // ---- S = (q@k^T) * scale * exp2(D - m_total), masked lower-tri ----
    {
        float dot[4][4];
#pragma unroll
        for (int u = 0; u < 4; u++)
#pragma unroll
            for (int w = 0; w < 4; w++) dot[u][w] = 0.f;
#pragma unroll 8
        for (int kkk = 0; kkk < DK_; kkk++) {
            float a[4], bb[4];
#pragma unroll
            for (int u = 0; u < 4; u++) a[u]  = q_s[(r0 + u) * P2_PAD + kkk];
#pragma unroll
            for (int w = 0; w < 4; w++) bb[w] = k_s[(c0 + w) * P2_PAD + kkk];
#pragma unroll
            for (int u = 0; u < 4; u++)
#pragma unroll
                for (int w = 0; w < 4; w++) dot[u][w] += a[u] * bb[w];
        }
#pragma unroll
        for (int u = 0; u < 4; u++) {
            int r = r0 + u;
#pragma unroll
            for (int w = 0; w < 4; w++) {
                int c = c0 + w;
                float sv = 0.f;
                if (c <= r)
                    sv = dot[u][w] * SCALE_F *
                         exp2f(vi_s[c] - b_s[c] + b_s[r] - mt_s[r]);
                S_s[r * P2_PAD + c] = sv;
            }
        }
    }
    __syncthreads();

    // ---- row sums + denominator ----
    if (tid < BT_) {
        int r = tid;
        float rs = 0.f;
        for (int c = 0; c < BT_; c++) rs += S_s[r * P2_PAD + c];
        float qn = 0.f;
        for (int kkk = 0; kkk < DK_; kkk++) qn += q_s[r * P2_PAD + kkk] * n_s[kkk];
        float dn = fmaxf(fabsf(qf_s[r] * qn + rs), exp2f(-mt_s[r]));
        rden_s[r] = 1.f / dn;
    }
    __syncthreads();

    // ---- h = (qf*(q@C) + S@v) * rden ----
    float acc1[4][4], acc2[4][4];
#pragma unroll
    for (int u = 0; u < 4; u++)
#pragma unroll
        for (int w = 0; w < 4; w++) { acc1[u][w] = 0.f; acc2[u][w] = 0.f; }

    const int j0 = tc * 4;
#pragma unroll 8
    for (int kkk = 0; kkk < DK_; kkk++) {
        float a[4], bb[4];
#pragma unroll
        for (int u = 0; u < 4; u++) a[u]  = q_s[(r0 + u) * P2_PAD + kkk];
#pragma unroll
        for (int w = 0; w < 4; w++) bb[w] = C_s[kkk * P2_PAD + j0 + w];
#pragma unroll
        for (int u = 0; u < 4; u++)
#pragma unroll
            for (int w = 0; w < 4; w++) acc1[u][w] += a[u] * bb[w];
    }
#pragma unroll 8
    for (int c = 0; c < BT_; c++) {
        float a[4], bb[4];
#pragma unroll
        for (int u = 0; u < 4; u++) a[u]  = S_s[(r0 + u) * P2_PAD + c];
#pragma unroll
        for (int w = 0; w < 4; w++) bb[w] = v_s[c * P2_PAD + j0 + w];
#pragma unroll
        for (int u = 0; u < 4; u++)
#pragma unroll
            for (int w = 0; w < 4; w++) acc2[u][w] += a[u] * bb[w];
    }

#pragma unroll
    for (int u = 0; u < 4; u++) {
        int r = r0 + u;
        float qf = qf_s[r], rd = rden_s[r];
        float4 o;
        o.x = (qf * acc1[u][0] + acc2[u][0]) * rd;
        o.y = (qf * acc1[u][1] + acc2[u][1]) * rd;
        o.z = (qf * acc1[u][2] + acc2[u][2]) * rd;
        o.w = (qf * acc1[u][3] + acc2[u][3]) * rd;
        *(float4*)&out[(base + r) * DV_ + j0] = o;
    }
}

// =======================================================================
extern "C" void kernel_launch(void* const* d_in, const int* in_sizes, int n_in,
                              void* d_out, int out_size)
{
    const float* q  = (const float*)d_in[0];
    const float* k  = (const float*)d_in[1];
    const float* v  = (const float*)d_in[2];
    const float* iv = (const float*)d_in[3];
    const float* fv = (const float*)d_in[4];
    float* out = (float*)d_out;

    cudaFuncSetAttribute(mlstm_pass2,
                         cudaFuncAttributeMaxDynamicSharedMemorySize,
                         SMEM2_BYTES);

    mlstm_pass1<<<dim3(BH_, VSPLIT), 256>>>(k, v, iv, fv);
    mlstm_pass2<<<dim3(NT_, BH_), 256, SMEM2_BYTES>>>(q, k, v, iv, out);
}